// round 2
// baseline (speedup 1.0000x reference)
#include <cuda_runtime.h>
#include <cstdint>

// KNRM: B=128, Q=16, D=1024, E=300, K=11
#define B_SZ 128
#define Q_SZ 16
#define D_SZ 1024
#define E_SZ 300
#define K_SZ 11
#define DC 64                      // doc rows per chunk
#define NCHUNK (D_SZ / DC)         // 16
#define NF4 75                     // 300 floats = 75 float4
#define QSTRIDE4 77                // padded float4 stride for q rows (bank-conflict-free)
#define DSTRIDE4 81                // padded float4 stride for d rows (bank-conflict-free)
#define DSTRIDEF (DSTRIDE4 * 4)    // 324 floats
#define DBUF_FLOATS (DC * DSTRIDEF)          // 20736 floats per buffer
#define QN_FLOATS (Q_SZ * QSTRIDE4 * 4)      // 4928 floats

#define SMEM_FLOATS (QN_FLOATS + 2 * DBUF_FLOATS + DC + Q_SZ + Q_SZ * 12)
#define SMEM_BYTES (SMEM_FLOATS * 4)         // 186,688 B

__device__ __forceinline__ float ex2f(float x) {
    float y;
    asm("ex2.approx.f32 %0, %1;" : "=f"(y) : "f"(x));
    return y;
}

__device__ __forceinline__ void cp_async16(uint32_t dst, const float* src) {
    asm volatile("cp.async.cg.shared.global [%0], [%1], 16;" :: "r"(dst), "l"(src));
}
#define CP_COMMIT() asm volatile("cp.async.commit_group;")
#define CP_WAIT1()  asm volatile("cp.async.wait_group 1;")

// Gather one 64-row chunk of doc embeddings into a smem buffer (async).
// thread t: row d = t&63, quarter fb = t>>6 handles f = fb, fb+4, fb+8, ...
__device__ __forceinline__ void prefetch_chunk(const int* __restrict__ toks,
                                               const float* __restrict__ emb,
                                               float* dbuf, int tid)
{
    int d  = tid & 63;
    int fb = tid >> 6;
    long tok = toks[d];
    const float* src = emb + tok * (long)E_SZ;
    uint32_t dst = (uint32_t)__cvta_generic_to_shared(dbuf + d * DSTRIDEF);
    for (int f = fb; f < NF4; f += 4)
        cp_async16(dst + (uint32_t)f * 16u, src + f * 4);
}

__global__ void __launch_bounds__(256, 1)
knrm_kernel(const int* __restrict__ doctoks, const int* __restrict__ querytoks,
            const float* __restrict__ emb, const float* __restrict__ mus,
            const float* __restrict__ sigmas, const float* __restrict__ fcw,
            const float* __restrict__ fcb, float* __restrict__ out)
{
    extern __shared__ float smem[];
    float4* qn4   = (float4*)smem;                 // raw query embeddings (permuted rows)
    float*  dsm   = smem + QN_FLOATS;              // 2 doc-chunk buffers
    float*  rnd_s = dsm + 2 * DBUF_FLOATS;         // 64 inverse doc norms
    float*  rnq_s = rnd_s + DC;                    // 16 inverse query norms
    float*  qfin  = rnq_s + Q_SZ;                  // 16 x 12 final accs
    float*  red   = dsm;                           // reduction buffer (aliases dsm)

    const int tid = threadIdx.x;
    const int b   = blockIdx.x;
    const int* dtoks_b = doctoks + b * D_SZ;

    // Kick off gather of chunks 0 and 1 immediately (overlaps query phase).
    prefetch_chunk(dtoks_b, emb, dsm, tid);
    CP_COMMIT();
    prefetch_chunk(dtoks_b + DC, emb, dsm + DBUF_FLOATS, tid);
    CP_COMMIT();

    // RBF constants: exp(-0.5 t^2/s^2) = 2^(c2 * t^2), c2 = -0.5*log2(e)/s^2
    float mu[K_SZ], c2[K_SZ];
#pragma unroll
    for (int k = 0; k < K_SZ; k++) {
        mu[k] = mus[k];
        float sg = sigmas[k];
        c2[k] = -0.72134752044448169f / (sg * sg);
    }

    // ---- Phase 1: load 16 query embeddings (raw) + inverse norms ----
    {
        int q = tid >> 4, p = tid & 15;
        int tok = querytoks[b * Q_SZ + q];
        const float4* src = (const float4*)(emb + (long)tok * E_SZ);
        int phys = ((q & 3) << 2) | (q >> 2);      // 4x4 transpose -> conflict-free GEMM reads
        float4* dst = qn4 + phys * QSTRIDE4;
        float ss = 0.f;
#pragma unroll
        for (int j = 0; j < 5; j++) {
            int f = p + 16 * j;
            if (f < NF4) {
                float4 v = src[f];
                dst[f] = v;
                ss += v.x * v.x + v.y * v.y + v.z * v.z + v.w * v.w;
            }
        }
        ss += __shfl_xor_sync(0xffffffffu, ss, 1);
        ss += __shfl_xor_sync(0xffffffffu, ss, 2);
        ss += __shfl_xor_sync(0xffffffffu, ss, 4);
        ss += __shfl_xor_sync(0xffffffffu, ss, 8);
        if (p == 0) rnq_s[q] = 1.f / (sqrtf(ss) + 1e-9f);
    }
    __syncthreads();

    // GEMM thread mapping: qg = tid&3 handles logical q = {4qg..4qg+3}; dl = tid>>2.
    const int qg = tid & 3;
    const int dl = tid >> 2;
    const float rq0 = rnq_s[qg * 4 + 0];
    const float rq1 = rnq_s[qg * 4 + 1];
    const float rq2 = rnq_s[qg * 4 + 2];
    const float rq3 = rnq_s[qg * 4 + 3];
    // physical row for logical q=4qg+j is j*4+qg
    const float4* q0p = qn4 + (0 * 4 + qg) * QSTRIDE4;
    const float4* q1p = qn4 + (1 * 4 + qg) * QSTRIDE4;
    const float4* q2p = qn4 + (2 * 4 + qg) * QSTRIDE4;
    const float4* q3p = qn4 + (3 * 4 + qg) * QSTRIDE4;

    float k0[K_SZ], k1[K_SZ], k2[K_SZ], k3[K_SZ];
#pragma unroll
    for (int k = 0; k < K_SZ; k++) { k0[k] = 0.f; k1[k] = 0.f; k2[k] = 0.f; k3[k] = 0.f; }
    float sm0 = 0.f, sm1 = 0.f, sm2 = 0.f, sm3 = 0.f;

    for (int c = 0; c < NCHUNK; c++) {
        float* dbuf = dsm + (c & 1) * DBUF_FLOATS;
        CP_WAIT1();                 // chunk c resident
        __syncthreads();

        // inverse norms of the 64 doc rows
        {
            int d = tid >> 2, p = tid & 3;
            const float4* row = (const float4*)(dbuf + d * DSTRIDEF);
            float ss = 0.f;
            for (int f = p; f < NF4; f += 4) {
                float4 v = row[f];
                ss += v.x * v.x + v.y * v.y + v.z * v.z + v.w * v.w;
            }
            ss += __shfl_xor_sync(0xffffffffu, ss, 1);
            ss += __shfl_xor_sync(0xffffffffu, ss, 2);
            if (p == 0) rnd_s[d] = 1.f / (sqrtf(ss) + 1e-9f);
        }
        __syncthreads();

        // ---- sim GEMM: 4 dots of length 300 per thread ----
        const float4* drow = (const float4*)(dbuf + dl * DSTRIDEF);
        float4 a0 = make_float4(0.f, 0.f, 0.f, 0.f);
        float4 a1 = a0, a2 = a0, a3 = a0;
#pragma unroll 5
        for (int f = 0; f < NF4; f++) {
            float4 dv = drow[f];
            float4 v0 = q0p[f];
            float4 v1 = q1p[f];
            float4 v2 = q2p[f];
            float4 v3 = q3p[f];
            a0.x = fmaf(v0.x, dv.x, a0.x); a0.y = fmaf(v0.y, dv.y, a0.y);
            a0.z = fmaf(v0.z, dv.z, a0.z); a0.w = fmaf(v0.w, dv.w, a0.w);
            a1.x = fmaf(v1.x, dv.x, a1.x); a1.y = fmaf(v1.y, dv.y, a1.y);
            a1.z = fmaf(v1.z, dv.z, a1.z); a1.w = fmaf(v1.w, dv.w, a1.w);
            a2.x = fmaf(v2.x, dv.x, a2.x); a2.y = fmaf(v2.y, dv.y, a2.y);
            a2.z = fmaf(v2.z, dv.z, a2.z); a2.w = fmaf(v2.w, dv.w, a2.w);
            a3.x = fmaf(v3.x, dv.x, a3.x); a3.y = fmaf(v3.y, dv.y, a3.y);
            a3.z = fmaf(v3.z, dv.z, a3.z); a3.w = fmaf(v3.w, dv.w, a3.w);
        }
        float rn = rnd_s[dl];
        float s0 = ((a0.x + a0.y) + (a0.z + a0.w)) * rn * rq0;
        float s1 = ((a1.x + a1.y) + (a1.z + a1.w)) * rn * rq1;
        float s2 = ((a2.x + a2.y) + (a2.z + a2.w)) * rn * rq2;
        float s3 = ((a3.x + a3.y) + (a3.z + a3.w)) * rn * rq3;
        sm0 += s0; sm1 += s1; sm2 += s2; sm3 += s3;

        // ---- RBF kernel bank (registers) ----
#pragma unroll
        for (int k = 0; k < K_SZ; k++) {
            float t;
            t = s0 - mu[k]; k0[k] += ex2f(c2[k] * t * t);
            t = s1 - mu[k]; k1[k] += ex2f(c2[k] * t * t);
            t = s2 - mu[k]; k2[k] += ex2f(c2[k] * t * t);
            t = s3 - mu[k]; k3[k] += ex2f(c2[k] * t * t);
        }

        __syncthreads();            // everyone done reading dbuf
        if (c + 2 < NCHUNK)
            prefetch_chunk(dtoks_b + (c + 2) * DC, emb, dbuf, tid);
        CP_COMMIT();                // always commit (keeps wait_group count aligned)
    }

    // ---- Reduce per-thread accumulators over the 64 d-lanes ----
    {
        float* r = red + tid * 49;
#pragma unroll
        for (int k = 0; k < K_SZ; k++) {
            r[k]      = k0[k];
            r[12 + k] = k1[k];
            r[24 + k] = k2[k];
            r[36 + k] = k3[k];
        }
        r[11] = sm0; r[23] = sm1; r[35] = sm2; r[47] = sm3;
    }
    __syncthreads();
    for (int idx = tid; idx < Q_SZ * 12; idx += 256) {
        int q = idx / 12, v = idx - q * 12;
        int qgr = q >> 2, j = q & 3;
        float sum = 0.f;
        for (int dd = 0; dd < DC; dd++)
            sum += red[(dd * 4 + qgr) * 49 + j * 12 + v];
        qfin[q * 12 + v] = sum;
    }
    __syncthreads();

    // ---- log, mask, Q-sum, FC head ----
    float partial = 0.f;
    if (tid < K_SZ) {
        float acc = 0.f;
        for (int q = 0; q < Q_SZ; q++)
            if (qfin[q * 12 + 11] != 0.0f)
                acc += logf(qfin[q * 12 + tid] + 1e-6f);
        partial = acc * fcw[tid];
    }
    if (tid < 32) {
#pragma unroll
        for (int m = 16; m; m >>= 1)
            partial += __shfl_xor_sync(0xffffffffu, partial, m);
        if (tid == 0) out[b] = partial + fcb[0];
    }
}

extern "C" void kernel_launch(void* const* d_in, const int* in_sizes, int n_in,
                              void* d_out, int out_size)
{
    const int*   doctoks   = (const int*)d_in[0];
    const int*   querytoks = (const int*)d_in[1];
    // d_in[2] = query_idf (unused by the reference)
    const float* emb       = (const float*)d_in[3];
    const float* mus       = (const float*)d_in[4];
    const float* sigmas    = (const float*)d_in[5];
    const float* fc_w      = (const float*)d_in[6];
    const float* fc_b      = (const float*)d_in[7];
    float* out = (float*)d_out;

    cudaFuncSetAttribute(knrm_kernel, cudaFuncAttributeMaxDynamicSharedMemorySize, SMEM_BYTES);
    knrm_kernel<<<B_SZ, 256, SMEM_BYTES>>>(doctoks, querytoks, emb, mus, sigmas,
                                           fc_w, fc_b, out);
}

// round 3
// speedup vs baseline: 1.4029x; 1.4029x over previous
#include <cuda_runtime.h>
#include <cstdint>

// KNRM: B=128, Q=16, D=1024, E=300, K=11
#define B_SZ 128
#define Q_SZ 16
#define D_SZ 1024
#define E_SZ 300
#define K_SZ 11
#define DC 64                       // doc rows per chunk
#define NCHUNK 16
#define NF4 75                      // 300 floats = 75 float4 (f4 index 75 is zero pad)
#define STR4 77                     // float4 row stride (77 ≡ 5 mod 8 -> bank spread)
#define ROWF (STR4 * 4)             // 308 floats per row
#define DBUF_F4 (DC * STR4)         // 4928 float4 per doc buffer
#define DBUF_FLOATS (DBUF_F4 * 4)   // 19712 floats
#define QN_F4 (Q_SZ * STR4)         // 1232
#define QN_FLOATS (QN_F4 * 4)       // 4928

#define SMEM_FLOATS (QN_FLOATS + 2 * DBUF_FLOATS + Q_SZ + Q_SZ * 12)
#define SMEM_BYTES (SMEM_FLOATS * 4)   // 178,240 B

__device__ __forceinline__ float ex2f(float x) {
    float y;
    asm("ex2.approx.f32 %0, %1;" : "=f"(y) : "f"(x));
    return y;
}

__device__ __forceinline__ void cp_async16(uint32_t dst, const float* src) {
    asm volatile("cp.async.cg.shared.global [%0], [%1], 16;" :: "r"(dst), "l"(src));
}
#define CP_COMMIT() asm volatile("cp.async.commit_group;")
#define CP_WAIT1()  asm volatile("cp.async.wait_group 1;")

// butterfly over the eq bits (lane bits 2,3): full sum across the 4 E-quarters
#define RED_EQ(v) { v += __shfl_xor_sync(0xffffffffu, v, 4); \
                    v += __shfl_xor_sync(0xffffffffu, v, 8); }

// Gather one 64-row chunk of doc embeddings into smem (async).
__device__ __forceinline__ void prefetch_chunk(const int* __restrict__ toks,
                                               const float* __restrict__ emb,
                                               float* dbuf, int tid)
{
    int d  = tid & 63;
    int fb = tid >> 6;
    long tok = toks[d];
    const float* src = emb + tok * (long)E_SZ;
    uint32_t dst = (uint32_t)__cvta_generic_to_shared(dbuf + d * ROWF);
    for (int f = fb; f < NF4; f += 4)
        cp_async16(dst + (uint32_t)f * 16u, src + f * 4);
}

__global__ void __launch_bounds__(256, 1)
knrm_kernel(const int* __restrict__ doctoks, const int* __restrict__ querytoks,
            const float* __restrict__ emb, const float* __restrict__ mus,
            const float* __restrict__ sigmas, const float* __restrict__ fcw,
            const float* __restrict__ fcb, float* __restrict__ out)
{
    extern __shared__ float smem[];
    float4* qn4   = (float4*)smem;                 // 16 query rows, stride 77 f4
    float*  dsm   = smem + QN_FLOATS;              // 2 doc-chunk buffers
    float*  rnq_s = dsm + 2 * DBUF_FLOATS;         // 16 inverse query norms
    float*  qfin  = rnq_s + Q_SZ;                  // 16 x 12 final accs
    float*  red   = dsm;                           // end-of-kernel reduction (aliases dsm)

    const int tid = threadIdx.x;
    const int b   = blockIdx.x;
    const int* dtoks_b = doctoks + b * D_SZ;

    // Kick off gather of chunks 0 and 1 immediately (overlaps query phase).
    prefetch_chunk(dtoks_b, emb, dsm, tid);
    CP_COMMIT();
    prefetch_chunk(dtoks_b + DC, emb, dsm + DBUF_FLOATS, tid);
    CP_COMMIT();

    // Zero the pad float4 (f4 index 75) of every row once.
    {
        float4 z = make_float4(0.f, 0.f, 0.f, 0.f);
        if (tid < Q_SZ) qn4[tid * STR4 + NF4] = z;
        if (tid < 2 * DC) {
            int buf = tid >> 6, r = tid & 63;
            ((float4*)dsm)[buf * DBUF_F4 + r * STR4 + NF4] = z;
        }
    }

    // RBF constants: exp(-0.5 t^2/s^2) = 2^(c2 * t^2)
    float mu[K_SZ], c2[K_SZ];
#pragma unroll
    for (int k = 0; k < K_SZ; k++) {
        mu[k] = mus[k];
        float sg = sigmas[k];
        c2[k] = -0.72134752044448169f / (sg * sg);
    }

    // ---- Phase 1: load 16 query embeddings (raw) + inverse norms ----
    {
        int q = tid >> 4, p = tid & 15;
        int tok = querytoks[b * Q_SZ + q];
        const float4* src = (const float4*)(emb + (long)tok * E_SZ);
        float4* dst = qn4 + q * STR4;
        float ss = 0.f;
#pragma unroll
        for (int j = 0; j < 5; j++) {
            int f = p + 16 * j;
            if (f < NF4) {
                float4 v = src[f];
                dst[f] = v;
                ss += v.x * v.x + v.y * v.y + v.z * v.z + v.w * v.w;
            }
        }
        ss += __shfl_xor_sync(0xffffffffu, ss, 1);
        ss += __shfl_xor_sync(0xffffffffu, ss, 2);
        ss += __shfl_xor_sync(0xffffffffu, ss, 4);
        ss += __shfl_xor_sync(0xffffffffu, ss, 8);
        if (p == 0) rnq_s[q] = 1.f / (sqrtf(ss) + 1e-9f);
    }
    __syncthreads();

    // Thread decomposition: tid = dg*16 + eq*4 + qg
    //   q rows handled for RBF: qg + 4*eq (one row, full)
    //   GEMM: 16 partial dots (q rows qg+4j, d rows 4dg + (qg^m)) over E-quarter eq.
    const int qg = tid & 3;
    const int eq = (tid >> 2) & 3;
    const int dg = tid >> 4;
    const int f0 = (eq == 0) ? 0  : (eq == 1) ? 20 : (eq == 2) ? 38 : 58;
    const int f1 = (eq == 0) ? 20 : (eq == 1) ? 38 : (eq == 2) ? 58 : 76;

    const float4* qp0 = qn4 + (qg +  0) * STR4;
    const float4* qp1 = qn4 + (qg +  4) * STR4;
    const float4* qp2 = qn4 + (qg +  8) * STR4;
    const float4* qp3 = qn4 + (qg + 12) * STR4;
    const int dr0 = (4 * dg + (qg ^ 0)) * STR4;
    const int dr1 = (4 * dg + (qg ^ 1)) * STR4;
    const int dr2 = (4 * dg + (qg ^ 2)) * STR4;
    const int dr3 = (4 * dg + (qg ^ 3)) * STR4;
    const float rq = rnq_s[qg + 4 * eq];

    float kq[K_SZ];
#pragma unroll
    for (int k = 0; k < K_SZ; k++) kq[k] = 0.f;
    float simsum = 0.f;

    for (int c = 0; c < NCHUNK; c++) {
        float* dbuf = dsm + (c & 1) * DBUF_FLOATS;
        CP_WAIT1();                 // chunk c resident
        __syncthreads();

        const float4* db4 = (const float4*)dbuf;

        float a00 = 0.f, a01 = 0.f, a02 = 0.f, a03 = 0.f;
        float a10 = 0.f, a11 = 0.f, a12 = 0.f, a13 = 0.f;
        float a20 = 0.f, a21 = 0.f, a22 = 0.f, a23 = 0.f;
        float a30 = 0.f, a31 = 0.f, a32 = 0.f, a33 = 0.f;
        float ssq = 0.f;            // sum of squares of d row 4dg+qg (m=0 slot)

        for (int f = f0; f < f1; f++) {
            float4 q0 = qp0[f];
            float4 q1 = qp1[f];
            float4 q2 = qp2[f];
            float4 q3 = qp3[f];
            float4 d0 = db4[dr0 + f];
            float4 d1 = db4[dr1 + f];
            float4 d2 = db4[dr2 + f];
            float4 d3 = db4[dr3 + f];

            ssq = fmaf(d0.x, d0.x, ssq); ssq = fmaf(d0.y, d0.y, ssq);
            ssq = fmaf(d0.z, d0.z, ssq); ssq = fmaf(d0.w, d0.w, ssq);

            a00 = fmaf(q0.x, d0.x, a00); a00 = fmaf(q0.y, d0.y, a00);
            a00 = fmaf(q0.z, d0.z, a00); a00 = fmaf(q0.w, d0.w, a00);
            a01 = fmaf(q0.x, d1.x, a01); a01 = fmaf(q0.y, d1.y, a01);
            a01 = fmaf(q0.z, d1.z, a01); a01 = fmaf(q0.w, d1.w, a01);
            a02 = fmaf(q0.x, d2.x, a02); a02 = fmaf(q0.y, d2.y, a02);
            a02 = fmaf(q0.z, d2.z, a02); a02 = fmaf(q0.w, d2.w, a02);
            a03 = fmaf(q0.x, d3.x, a03); a03 = fmaf(q0.y, d3.y, a03);
            a03 = fmaf(q0.z, d3.z, a03); a03 = fmaf(q0.w, d3.w, a03);

            a10 = fmaf(q1.x, d0.x, a10); a10 = fmaf(q1.y, d0.y, a10);
            a10 = fmaf(q1.z, d0.z, a10); a10 = fmaf(q1.w, d0.w, a10);
            a11 = fmaf(q1.x, d1.x, a11); a11 = fmaf(q1.y, d1.y, a11);
            a11 = fmaf(q1.z, d1.z, a11); a11 = fmaf(q1.w, d1.w, a11);
            a12 = fmaf(q1.x, d2.x, a12); a12 = fmaf(q1.y, d2.y, a12);
            a12 = fmaf(q1.z, d2.z, a12); a12 = fmaf(q1.w, d2.w, a12);
            a13 = fmaf(q1.x, d3.x, a13); a13 = fmaf(q1.y, d3.y, a13);
            a13 = fmaf(q1.z, d3.z, a13); a13 = fmaf(q1.w, d3.w, a13);

            a20 = fmaf(q2.x, d0.x, a20); a20 = fmaf(q2.y, d0.y, a20);
            a20 = fmaf(q2.z, d0.z, a20); a20 = fmaf(q2.w, d0.w, a20);
            a21 = fmaf(q2.x, d1.x, a21); a21 = fmaf(q2.y, d1.y, a21);
            a21 = fmaf(q2.z, d1.z, a21); a21 = fmaf(q2.w, d1.w, a21);
            a22 = fmaf(q2.x, d2.x, a22); a22 = fmaf(q2.y, d2.y, a22);
            a22 = fmaf(q2.z, d2.z, a22); a22 = fmaf(q2.w, d2.w, a22);
            a23 = fmaf(q2.x, d3.x, a23); a23 = fmaf(q2.y, d3.y, a23);
            a23 = fmaf(q2.z, d3.z, a23); a23 = fmaf(q2.w, d3.w, a23);

            a30 = fmaf(q3.x, d0.x, a30); a30 = fmaf(q3.y, d0.y, a30);
            a30 = fmaf(q3.z, d0.z, a30); a30 = fmaf(q3.w, d0.w, a30);
            a31 = fmaf(q3.x, d1.x, a31); a31 = fmaf(q3.y, d1.y, a31);
            a31 = fmaf(q3.z, d1.z, a31); a31 = fmaf(q3.w, d1.w, a31);
            a32 = fmaf(q3.x, d2.x, a32); a32 = fmaf(q3.y, d2.y, a32);
            a32 = fmaf(q3.z, d2.z, a32); a32 = fmaf(q3.w, d2.w, a32);
            a33 = fmaf(q3.x, d3.x, a33); a33 = fmaf(q3.y, d3.y, a33);
            a33 = fmaf(q3.z, d3.z, a33); a33 = fmaf(q3.w, d3.w, a33);
        }

        // dbuf fully consumed by this thread; sync, then start the next gather
        // so cp.async overlaps the butterfly/RBF tail below.
        __syncthreads();
        if (c + 2 < NCHUNK)
            prefetch_chunk(dtoks_b + (c + 2) * DC, emb, dbuf, tid);
        CP_COMMIT();

        // Combine E-quarters (eq = lane bits 2,3).
        RED_EQ(a00); RED_EQ(a01); RED_EQ(a02); RED_EQ(a03);
        RED_EQ(a10); RED_EQ(a11); RED_EQ(a12); RED_EQ(a13);
        RED_EQ(a20); RED_EQ(a21); RED_EQ(a22); RED_EQ(a23);
        RED_EQ(a30); RED_EQ(a31); RED_EQ(a32); RED_EQ(a33);
        RED_EQ(ssq);

        // Inverse doc norms: thread owns row 4dg+qg; gather the other three
        // (qg = lane bits 0,1).
        float rn0 = 1.f / (sqrtf(ssq) + 1e-9f);
        float rn1 = __shfl_xor_sync(0xffffffffu, rn0, 1);
        float rn2 = __shfl_xor_sync(0xffffffffu, rn0, 2);
        float rn3 = __shfl_xor_sync(0xffffffffu, rn1, 2);

        // Select this thread's RBF row (j = eq).
        float c0, c1, c2v, c3v;
        if (eq == 0)      { c0 = a00; c1 = a01; c2v = a02; c3v = a03; }
        else if (eq == 1) { c0 = a10; c1 = a11; c2v = a12; c3v = a13; }
        else if (eq == 2) { c0 = a20; c1 = a21; c2v = a22; c3v = a23; }
        else              { c0 = a30; c1 = a31; c2v = a32; c3v = a33; }

        float s0 = c0  * rn0 * rq;
        float s1 = c1  * rn1 * rq;
        float s2 = c2v * rn2 * rq;
        float s3 = c3v * rn3 * rq;
        simsum += (s0 + s1) + (s2 + s3);

#pragma unroll
        for (int k = 0; k < K_SZ; k++) {
            float t;
            t = s0 - mu[k]; kq[k] += ex2f(c2[k] * t * t);
            t = s1 - mu[k]; kq[k] += ex2f(c2[k] * t * t);
            t = s2 - mu[k]; kq[k] += ex2f(c2[k] * t * t);
            t = s3 - mu[k]; kq[k] += ex2f(c2[k] * t * t);
        }
    }

    // ---- Final reduction: sum per (q, value) over the 16 dg threads ----
    __syncthreads();
    {
        float* r = red + tid * 13;
#pragma unroll
        for (int k = 0; k < K_SZ; k++) r[k] = kq[k];
        r[11] = simsum;
    }
    __syncthreads();
    for (int idx = tid; idx < Q_SZ * 12; idx += 256) {
        int q = idx / 12, v = idx - q * 12;
        int eqr = q >> 2, qgr = q & 3;
        float sum = 0.f;
        for (int d = 0; d < 16; d++)
            sum += red[(d * 16 + eqr * 4 + qgr) * 13 + v];
        qfin[q * 12 + v] = sum;
    }
    __syncthreads();

    // ---- log, mask, Q-sum, FC head ----
    float partial = 0.f;
    if (tid < K_SZ) {
        float acc = 0.f;
        for (int q = 0; q < Q_SZ; q++)
            if (qfin[q * 12 + 11] != 0.0f)
                acc += logf(qfin[q * 12 + tid] + 1e-6f);
        partial = acc * fcw[tid];
    }
    if (tid < 32) {
#pragma unroll
        for (int m = 16; m; m >>= 1)
            partial += __shfl_xor_sync(0xffffffffu, partial, m);
        if (tid == 0) out[b] = partial + fcb[0];
    }
}

extern "C" void kernel_launch(void* const* d_in, const int* in_sizes, int n_in,
                              void* d_out, int out_size)
{
    const int*   doctoks   = (const int*)d_in[0];
    const int*   querytoks = (const int*)d_in[1];
    // d_in[2] = query_idf (unused by the reference)
    const float* emb       = (const float*)d_in[3];
    const float* mus       = (const float*)d_in[4];
    const float* sigmas    = (const float*)d_in[5];
    const float* fc_w      = (const float*)d_in[6];
    const float* fc_b      = (const float*)d_in[7];
    float* out = (float*)d_out;

    cudaFuncSetAttribute(knrm_kernel, cudaFuncAttributeMaxDynamicSharedMemorySize, SMEM_BYTES);
    knrm_kernel<<<B_SZ, 256, SMEM_BYTES>>>(doctoks, querytoks, emb, mus, sigmas,
                                           fc_w, fc_b, out);
}